// round 15
// baseline (speedup 1.0000x reference)
#include <cuda_runtime.h>
#include <math.h>
#include <stdint.h>

#define N_NODES   50000
#define N_EDGES   600000
#define IN_DIM    64
#define D         128
#define N_LAYERS  8
#define N_ETYPES  44
#define N_MENTIONS 100000
#define N_VARS    20000
#define OUT_DIM   100

// ---------------- scratch ----------------
__device__ float g_h[N_NODES * D];
__device__ float g_t[N_NODES * D];
__device__ float g_PQ[N_NODES * 512];            // [n][0:256]=P(dst), [n][256:512]=Q(src)
__device__ float g_R[N_LAYERS * N_ETYPES * 256];
__device__ float g_S[N_NODES * 256];
__device__ float g_Wcat[N_LAYERS * 128 * 512];   // [l][k][0:256]=W1[k], [256:512]=W1[128+k]
__device__ float g_vsum[N_VARS * D];
__device__ float g_vcnt[N_VARS];
__device__ float g_vrep[N_VARS * D];
// sort scratch
__device__ int   g_deg[N_NODES];
__device__ int   g_cur[N_NODES];
__device__ float g_degf[N_NODES];
__device__ int   g_part[256];
__device__ int   g_spk[N_EDGES];                 // src | (lab<<16)
__device__ int   g_sdst[N_EDGES];

__device__ __forceinline__ void red2(float* p, float x, float y) {
    asm volatile("red.global.add.v2.f32 [%0], {%1, %2};" :: "l"(p), "f"(x), "f"(y) : "memory");
}

// ---------------- sgemm128: 128x128 tile, 8x8 micro, reg-prefetch double buffer ----------------
// Requires: N % 128 == 0, K % 16 == 0. M guarded. act: 0=none,1=relu,2=gelu.
__global__ __launch_bounds__(256, 2)
void sgemm128_kernel(const float* __restrict__ A, int lda,
                     const float* __restrict__ B, int ldb,
                     const float* __restrict__ bias,
                     const float* __restrict__ rowscale,
                     float* __restrict__ C, int ldc,
                     int M, int N, int K, int act)
{
    __shared__ __align__(16) float As[2][16][132];   // [buf][k][m]
    __shared__ __align__(16) float Bs[2][16][128];   // [buf][k][n]
    const int tid = threadIdx.x;
    const int m0 = blockIdx.y * 128, n0 = blockIdx.x * 128;
    const int tx = tid & 15, ty = tid >> 4;

    const int aC = tid & 15;          // k-col for A loads
    const int aR = tid >> 4;          // base row (0..15), rows aR+p*16
    const int bR = tid >> 5;          // base k (0..7), k = bR+p*8
    const int bC = (tid & 31) * 4;    // n-col

    float acc[8][8];
#pragma unroll
    for (int i = 0; i < 8; i++)
#pragma unroll
        for (int j = 0; j < 8; j++) acc[i][j] = 0.f;

    float pa[8];
    float4 pb[2];
    const int KT = K >> 4;

    // prologue: tile 0
    {
#pragma unroll
        for (int p = 0; p < 8; p++) {
            int m = m0 + aR + p * 16;
            pa[p] = (m < M) ? A[(size_t)m * lda + aC] : 0.f;
        }
#pragma unroll
        for (int p = 0; p < 2; p++)
            pb[p] = *(const float4*)&B[(size_t)(bR + p * 8) * ldb + n0 + bC];
#pragma unroll
        for (int p = 0; p < 8; p++) As[0][aC][aR + p * 16] = pa[p];
#pragma unroll
        for (int p = 0; p < 2; p++) *(float4*)&Bs[0][bR + p * 8][bC] = pb[p];
    }
    __syncthreads();

    for (int kt = 0; kt < KT; kt++) {
        const int b = kt & 1;
        if (kt + 1 < KT) {
            const int k0 = (kt + 1) * 16;
#pragma unroll
            for (int p = 0; p < 8; p++) {
                int m = m0 + aR + p * 16;
                pa[p] = (m < M) ? A[(size_t)m * lda + k0 + aC] : 0.f;
            }
#pragma unroll
            for (int p = 0; p < 2; p++)
                pb[p] = *(const float4*)&B[(size_t)(k0 + bR + p * 8) * ldb + n0 + bC];
        }
#pragma unroll
        for (int kk = 0; kk < 16; kk++) {
            float4 a0 = *(const float4*)&As[b][kk][ty * 8];
            float4 a1 = *(const float4*)&As[b][kk][ty * 8 + 4];
            float4 b0 = *(const float4*)&Bs[b][kk][tx * 8];
            float4 b1 = *(const float4*)&Bs[b][kk][tx * 8 + 4];
            float av[8] = {a0.x, a0.y, a0.z, a0.w, a1.x, a1.y, a1.z, a1.w};
            float bv[8] = {b0.x, b0.y, b0.z, b0.w, b1.x, b1.y, b1.z, b1.w};
#pragma unroll
            for (int i = 0; i < 8; i++)
#pragma unroll
                for (int j = 0; j < 8; j++)
                    acc[i][j] += av[i] * bv[j];
        }
        if (kt + 1 < KT) {
            const int nb = (kt + 1) & 1;
#pragma unroll
            for (int p = 0; p < 8; p++) As[nb][aC][aR + p * 16] = pa[p];
#pragma unroll
            for (int p = 0; p < 2; p++) *(float4*)&Bs[nb][bR + p * 8][bC] = pb[p];
            __syncthreads();
        }
    }

    // epilogue
#pragma unroll
    for (int i = 0; i < 8; i++) {
        int m = m0 + ty * 8 + i;
        if (m >= M) continue;
        float rs = rowscale ? rowscale[m] : 1.f;
#pragma unroll
        for (int jh = 0; jh < 2; jh++) {
            int n = n0 + tx * 8 + jh * 4;
            float4 v;
            v.x = acc[i][jh * 4 + 0];
            v.y = acc[i][jh * 4 + 1];
            v.z = acc[i][jh * 4 + 2];
            v.w = acc[i][jh * 4 + 3];
            if (bias) {
                v.x += rs * bias[n + 0];
                v.y += rs * bias[n + 1];
                v.z += rs * bias[n + 2];
                v.w += rs * bias[n + 3];
            }
            if (act == 1) {
                v.x = fmaxf(v.x, 0.f); v.y = fmaxf(v.y, 0.f);
                v.z = fmaxf(v.z, 0.f); v.w = fmaxf(v.w, 0.f);
            } else if (act == 2) {
                v.x = 0.5f * v.x * (1.f + erff(v.x * 0.70710678118654752f));
                v.y = 0.5f * v.y * (1.f + erff(v.y * 0.70710678118654752f));
                v.z = 0.5f * v.z * (1.f + erff(v.z * 0.70710678118654752f));
                v.w = 0.5f * v.w * (1.f + erff(v.w * 0.70710678118654752f));
            }
            *(float4*)&C[(size_t)m * ldc + n] = v;
        }
    }
}

// ---------------- small-N SGEMM (decoder final, N=100) ----------------
__global__ void sgemm_kernel(const float* __restrict__ A, int lda,
                             const float* __restrict__ B, int ldb,
                             const float* __restrict__ bias,
                             float* __restrict__ C, int ldc,
                             int M, int N, int K, int act)
{
    __shared__ __align__(16) float As[16][68];
    __shared__ __align__(16) float Bs[16][64];
    const int tid = threadIdx.x;
    const int m0 = blockIdx.y * 64, n0 = blockIdx.x * 64;
    const int ty = tid >> 4, tx = tid & 15;

    float acc[4][4];
#pragma unroll
    for (int i = 0; i < 4; i++)
#pragma unroll
        for (int j = 0; j < 4; j++) acc[i][j] = 0.f;

    for (int k0 = 0; k0 < K; k0 += 16) {
        {
            int r = tid >> 4, c = tid & 15;
#pragma unroll
            for (int p = 0; p < 4; p++) {
                int m = m0 + p * 16 + r;
                As[c][p * 16 + r] = (m < M) ? A[(size_t)m * lda + k0 + c] : 0.f;
            }
        }
        {
            int r = tid >> 6, c = tid & 63;
#pragma unroll
            for (int p = 0; p < 4; p++) {
                int k = k0 + p * 4 + r, n = n0 + c;
                Bs[p * 4 + r][c] = (n < N) ? B[(size_t)k * ldb + n] : 0.f;
            }
        }
        __syncthreads();
#pragma unroll
        for (int kk = 0; kk < 16; kk++) {
            float4 a4 = *(const float4*)&As[kk][ty * 4];
            float4 b4 = *(const float4*)&Bs[kk][tx * 4];
            acc[0][0] += a4.x * b4.x; acc[0][1] += a4.x * b4.y; acc[0][2] += a4.x * b4.z; acc[0][3] += a4.x * b4.w;
            acc[1][0] += a4.y * b4.x; acc[1][1] += a4.y * b4.y; acc[1][2] += a4.y * b4.z; acc[1][3] += a4.y * b4.w;
            acc[2][0] += a4.z * b4.x; acc[2][1] += a4.z * b4.y; acc[2][2] += a4.z * b4.z; acc[2][3] += a4.z * b4.w;
            acc[3][0] += a4.w * b4.x; acc[3][1] += a4.w * b4.y; acc[3][2] += a4.w * b4.z; acc[3][3] += a4.w * b4.w;
        }
        __syncthreads();
    }
#pragma unroll
    for (int i = 0; i < 4; i++) {
        int m = m0 + ty * 4 + i;
        if (m >= M) continue;
#pragma unroll
        for (int j = 0; j < 4; j++) {
            int n = n0 + tx * 4 + j;
            if (n >= N) continue;
            float v = acc[i][j] + (bias ? bias[n] : 0.f);
            if (act == 1) v = fmaxf(v, 0.f);
            C[(size_t)m * ldc + n] = v;
        }
    }
}

// ---------------- per-etype R table ----------------
__global__ void r_kernel(const float* __restrict__ edge_emb,
                         const float* __restrict__ mlp_W1,
                         const float* __restrict__ mlp_b1,
                         float* __restrict__ R)
{
    int l = blockIdx.y, e = blockIdx.x, j = threadIdx.x;
    __shared__ float emb[128];
    if (j < 128) emb[j] = edge_emb[(l * N_ETYPES + e) * 128 + j];
    __syncthreads();
    const float* W = mlp_W1 + ((size_t)l * 384 + 256) * 256;
    float s = mlp_b1[l * 256 + j];
#pragma unroll 8
    for (int k = 0; k < 128; k++) s += emb[k] * W[k * 256 + j];
    R[((size_t)l * N_ETYPES + e) * 256 + j] = s;
}

// ---------------- Wcat: [l][k][0:256]=W1[k,:], [256:512]=W1[128+k,:] ----------------
__global__ void wcat_kernel(const float* __restrict__ mlp_W1) {
    int l = blockIdx.y;
    int idx = blockIdx.x * 256 + threadIdx.x;
    if (idx >= 128 * 512) return;
    int k = idx >> 9, j = idx & 511;
    float v = (j < 256) ? mlp_W1[((size_t)l * 384 + k) * 256 + j]
                        : mlp_W1[((size_t)l * 384 + 128 + k) * 256 + (j - 256)];
    g_Wcat[((size_t)l * 128 + k) * 512 + j] = v;
}

// ---------------- counting sort by dst ----------------
__global__ void zero_int_kernel(int* p, int n) {
    int i = blockIdx.x * blockDim.x + threadIdx.x;
    if (i < n) p[i] = 0;
}
__global__ void hist_kernel(const int* __restrict__ edges) {
    int e = blockIdx.x * blockDim.x + threadIdx.x;
    if (e < N_EDGES) atomicAdd(&g_deg[edges[N_EDGES + e]], 1);
}
#define SCAN_B 512
__global__ void scan1_kernel() {
    __shared__ int s[SCAN_B];
    int i = blockIdx.x * SCAN_B + threadIdx.x;
    s[threadIdx.x] = (i < N_NODES) ? g_deg[i] : 0;
    __syncthreads();
    for (int off = SCAN_B / 2; off > 0; off >>= 1) {
        if (threadIdx.x < off) s[threadIdx.x] += s[threadIdx.x + off];
        __syncthreads();
    }
    if (threadIdx.x == 0) g_part[blockIdx.x] = s[0];
}
__global__ void scan2_kernel(int nb) {
    __shared__ int s[256];
    s[threadIdx.x] = (threadIdx.x < nb) ? g_part[threadIdx.x] : 0;
    __syncthreads();
    if (threadIdx.x < nb) {
        int sum = 0;
        for (int j = 0; j < threadIdx.x; j++) sum += s[j];
        g_part[threadIdx.x] = sum;
    }
}
__global__ void scan3_kernel() {
    __shared__ int s[SCAN_B];
    int i = blockIdx.x * SCAN_B + threadIdx.x;
    int v = (i < N_NODES) ? g_deg[i] : 0;
    s[threadIdx.x] = v;
    __syncthreads();
    for (int o = 1; o < SCAN_B; o <<= 1) {
        int t = (threadIdx.x >= o) ? s[threadIdx.x - o] : 0;
        __syncthreads();
        s[threadIdx.x] += t;
        __syncthreads();
    }
    if (i < N_NODES) {
        int excl = s[threadIdx.x] - v + g_part[blockIdx.x];
        g_cur[i] = excl;
        g_degf[i] = (float)v;
    }
}
__global__ void sort_kernel(const int* __restrict__ edges, const int* __restrict__ elab) {
    int e = blockIdx.x * blockDim.x + threadIdx.x;
    if (e >= N_EDGES) return;
    int d = edges[N_EDGES + e];
    int p = atomicAdd(&g_cur[d], 1);
    g_spk[p] = edges[e] | (elab[e] << 16);
    g_sdst[p] = d;
}

// ---------------- edge pass: S[dst] += relu(P[dst]+Q[src]+R[lab]) ----------------
#define EPB 1024
__global__ __launch_bounds__(256)
void edge_kernel(const float* __restrict__ Rl)
{
    const int w = threadIdx.x >> 5, lane = threadIdx.x & 31;
    int e0 = blockIdx.x * EPB + w * (EPB / 8);
    int e1 = e0 + (EPB / 8);
    if (e1 > N_EDGES) e1 = N_EDGES;
    if (e0 >= e1) return;
    const int l4 = lane * 4;

    float4 a0 = make_float4(0.f, 0.f, 0.f, 0.f);
    float4 a1 = make_float4(0.f, 0.f, 0.f, 0.f);
    int cur = g_sdst[e0];
    const float* Pb = g_PQ + (size_t)cur * 512;
    float4 P0 = *(const float4*)(Pb + l4);
    float4 P1 = *(const float4*)(Pb + 128 + l4);

    for (int e = e0; e < e1; ++e) {
        int d = g_sdst[e];
        if (d != cur) {
            float* S = g_S + (size_t)cur * 256 + l4;
            red2(S,       a0.x, a0.y); red2(S + 2,   a0.z, a0.w);
            red2(S + 128, a1.x, a1.y); red2(S + 130, a1.z, a1.w);
            a0 = make_float4(0.f, 0.f, 0.f, 0.f);
            a1 = make_float4(0.f, 0.f, 0.f, 0.f);
            cur = d;
            const float* Pn = g_PQ + (size_t)cur * 512;
            P0 = *(const float4*)(Pn + l4);
            P1 = *(const float4*)(Pn + 128 + l4);
        }
        int v = g_spk[e];
        int s = v & 0xFFFF, lb = v >> 16;
        const float* Q = g_PQ + (size_t)s * 512 + 256;
        float4 q0 = *(const float4*)(Q + l4);
        float4 q1 = *(const float4*)(Q + 128 + l4);
        const float* Rp = Rl + lb * 256;
        float4 r0 = *(const float4*)(Rp + l4);
        float4 r1 = *(const float4*)(Rp + 128 + l4);
        a0.x += fmaxf(P0.x + q0.x + r0.x, 0.f);
        a0.y += fmaxf(P0.y + q0.y + r0.y, 0.f);
        a0.z += fmaxf(P0.z + q0.z + r0.z, 0.f);
        a0.w += fmaxf(P0.w + q0.w + r0.w, 0.f);
        a1.x += fmaxf(P1.x + q1.x + r1.x, 0.f);
        a1.y += fmaxf(P1.y + q1.y + r1.y, 0.f);
        a1.z += fmaxf(P1.z + q1.z + r1.z, 0.f);
        a1.w += fmaxf(P1.w + q1.w + r1.w, 0.f);
    }
    float* S = g_S + (size_t)cur * 256 + l4;
    red2(S,       a0.x, a0.y); red2(S + 2,   a0.z, a0.w);
    red2(S + 128, a1.x, a1.y); red2(S + 130, a1.z, a1.w);
}

// ---------------- small elementwise kernels ----------------
__global__ void zero4_kernel(float4* p, int n4) {
    int i = blockIdx.x * blockDim.x + threadIdx.x;
    if (i < n4) p[i] = make_float4(0.f, 0.f, 0.f, 0.f);
}
__global__ void zero_kernel(float* p, int n) {
    int i = blockIdx.x * blockDim.x + threadIdx.x;
    if (i < n) p[i] = 0.f;
}
__global__ void scatter_kernel(const int* __restrict__ vg, const int* __restrict__ vs) {
    int i = blockIdx.x * blockDim.x + threadIdx.x;
    if (i >= N_MENTIONS * D) return;
    int m = i >> 7, c = i & 127;
    int v = vs[m], n = vg[m];
    atomicAdd(&g_vsum[v * D + c], g_h[n * D + c]);
    if (c == 0) atomicAdd(&g_vcnt[v], 1.0f);
}
__global__ void vrep_kernel() {
    int i = blockIdx.x * blockDim.x + threadIdx.x;
    if (i >= N_VARS * D) return;
    int v = i >> 7;
    g_vrep[i] = g_vsum[i] / fmaxf(g_vcnt[v], 1.0f);
}

// ---------------- host ----------------
static void launch_sgemm128(const float* A, int lda, const float* B, int ldb, const float* bias,
                            const float* rowscale, float* C, int ldc, int M, int N, int K, int act)
{
    dim3 grid(N / 128, (M + 127) / 128);
    sgemm128_kernel<<<grid, 256>>>(A, lda, B, ldb, bias, rowscale, C, ldc, M, N, K, act);
}

extern "C" void kernel_launch(void* const* d_in, const int* in_sizes, int n_in,
                              void* d_out, int out_size)
{
    const float* node_labels = (const float*)d_in[0];
    const int*   edges       = (const int*)d_in[1];
    const int*   elab        = (const int*)d_in[2];
    const int*   vg          = (const int*)d_in[3];
    const int*   vs          = (const int*)d_in[4];
    int w = (n_in >= 20 && in_sizes[6] == 1) ? 7 : 6;
    const float* enc_W0  = (const float*)d_in[w + 0];
    const float* enc_b0  = (const float*)d_in[w + 1];
    const float* enc_W1  = (const float*)d_in[w + 2];
    const float* enc_b1  = (const float*)d_in[w + 3];
    const float* edge_emb= (const float*)d_in[w + 4];
    const float* mlp_W1  = (const float*)d_in[w + 5];
    const float* mlp_b1  = (const float*)d_in[w + 6];
    const float* mlp_W2  = (const float*)d_in[w + 7];
    const float* mlp_b2  = (const float*)d_in[w + 8];
    const float* dec_W0  = (const float*)d_in[w + 9];
    const float* dec_b0  = (const float*)d_in[w + 10];
    const float* dec_Wl  = (const float*)d_in[w + 11];
    const float* dec_bl  = (const float*)d_in[w + 12];
    float* out = (float*)d_out;

    float *h, *t, *PQ, *R, *S, *Wcat, *vsum, *vcnt, *vrep, *degf;
    int *deg;
    cudaGetSymbolAddress((void**)&h,    g_h);
    cudaGetSymbolAddress((void**)&t,    g_t);
    cudaGetSymbolAddress((void**)&PQ,   g_PQ);
    cudaGetSymbolAddress((void**)&R,    g_R);
    cudaGetSymbolAddress((void**)&S,    g_S);
    cudaGetSymbolAddress((void**)&Wcat, g_Wcat);
    cudaGetSymbolAddress((void**)&vsum, g_vsum);
    cudaGetSymbolAddress((void**)&vcnt, g_vcnt);
    cudaGetSymbolAddress((void**)&vrep, g_vrep);
    cudaGetSymbolAddress((void**)&degf, g_degf);
    cudaGetSymbolAddress((void**)&deg,  g_deg);

    const int NB = (N_NODES + SCAN_B - 1) / SCAN_B;

    // ---- counting sort of edges by dst ----
    zero_int_kernel<<<(N_NODES + 255) / 256, 256>>>(deg, N_NODES);
    hist_kernel<<<(N_EDGES + 255) / 256, 256>>>(edges);
    scan1_kernel<<<NB, SCAN_B>>>();
    scan2_kernel<<<1, 256>>>(NB);
    scan3_kernel<<<NB, SCAN_B>>>();
    sort_kernel<<<(N_EDGES + 255) / 256, 256>>>(edges, elab);

    // ---- tables ----
    r_kernel<<<dim3(N_ETYPES, N_LAYERS), 256>>>(edge_emb, mlp_W1, mlp_b1, R);
    wcat_kernel<<<dim3((128 * 512 + 255) / 256, N_LAYERS), 256>>>(mlp_W1);

    // ---- encoder ----
    launch_sgemm128(node_labels, IN_DIM, enc_W0, D, enc_b0, nullptr, t, D, N_NODES, D, IN_DIM, 1);
    launch_sgemm128(t, D, enc_W1, D, enc_b1, nullptr, h, D, N_NODES, D, D, 0);

    // ---- GGNN layers ----
    for (int l = 0; l < N_LAYERS; l++) {
        launch_sgemm128(h, D, Wcat + (size_t)l * 128 * 512, 512, nullptr, nullptr,
                        PQ, 512, N_NODES, 512, D, 0);
        zero4_kernel<<<(N_NODES * 64 + 255) / 256, 256>>>((float4*)S, N_NODES * 64);
        edge_kernel<<<(N_EDGES + EPB - 1) / EPB, 256>>>(R + (size_t)l * N_ETYPES * 256);
        launch_sgemm128(S, 256, mlp_W2 + (size_t)l * 256 * 128, 128,
                        mlp_b2 + (size_t)l * 128, degf, h, D, N_NODES, 128, 256, 2);
    }

    // ---- readout ----
    zero4_kernel<<<(N_VARS * 32 + 255) / 256, 256>>>((float4*)vsum, N_VARS * 32);
    zero_kernel<<<(N_VARS + 255) / 256, 256>>>(vcnt, N_VARS);
    scatter_kernel<<<(N_MENTIONS * D + 255) / 256, 256>>>(vg, vs);
    vrep_kernel<<<(N_VARS * D + 255) / 256, 256>>>();

    // ---- decoder ----
    launch_sgemm128(vrep, D, dec_W0, D, dec_b0, nullptr, t, D, N_VARS, D, D, 1);
    {
        dim3 grid((OUT_DIM + 63) / 64, (N_VARS + 63) / 64);
        sgemm_kernel<<<grid, 256>>>(t, D, dec_Wl, OUT_DIM, dec_bl, out, OUT_DIM, N_VARS, OUT_DIM, D, 0);
    }
}